// round 11
// baseline (speedup 1.0000x reference)
#include <cuda_runtime.h>
#include <cuda_fp16.h>
#include <cstdint>

#define XD 128
#define YD 128
#define ZD 8
#define ED 64
#define NITER 3
#define FHD 96
#define FWD 320
#define NPTS (XD*YD*ZD)
#define HW (FHD*FWD)

typedef unsigned long long ull;

__device__ __half g_imgTh[HW * ED];   // (H,W,C) fp16 image, 3.9 MB

__device__ __forceinline__ ull pk2(float x, float y) {
    ull r; asm("mov.b64 %0,{%1,%2};" : "=l"(r) : "f"(x), "f"(y)); return r;
}
__device__ __forceinline__ ull splat(float x) { return pk2(x, x); }
__device__ __forceinline__ void unpk(ull v, float& x, float& y) {
    asm("mov.b64 {%0,%1},%2;" : "=f"(x), "=f"(y) : "l"(v));
}
__device__ __forceinline__ ull fma2(ull a, ull b, ull c) {
    ull d; asm("fma.rn.f32x2 %0,%1,%2,%3;" : "=l"(d) : "l"(a), "l"(b), "l"(c)); return d;
}
__device__ __forceinline__ ull add2(ull a, ull b) {
    ull d; asm("add.rn.f32x2 %0,%1,%2;" : "=l"(d) : "l"(a), "l"(b)); return d;
}
__device__ __forceinline__ uint32_t smem_u32(const void* p) {
    uint32_t a; asm("{ .reg .u64 t; cvta.to.shared.u64 t, %1; cvt.u32.u64 %0, t; }" : "=r"(a) : "l"(p));
    return a;
}

#define SWZ(off) ((off) ^ (((off) >> 3) & 0x70))

__device__ __forceinline__ void ldsm_x4(uint32_t& r0, uint32_t& r1, uint32_t& r2, uint32_t& r3,
                                        uint32_t addr) {
    asm volatile("ldmatrix.sync.aligned.m8n8.x4.shared.b16 {%0,%1,%2,%3}, [%4];"
                 : "=r"(r0), "=r"(r1), "=r"(r2), "=r"(r3) : "r"(addr));
}
__device__ __forceinline__ void ldsm_x4t(uint32_t& r0, uint32_t& r1, uint32_t& r2, uint32_t& r3,
                                         uint32_t addr) {
    asm volatile("ldmatrix.sync.aligned.m8n8.x4.trans.shared.b16 {%0,%1,%2,%3}, [%4];"
                 : "=r"(r0), "=r"(r1), "=r"(r2), "=r"(r3) : "r"(addr));
}
__device__ __forceinline__ void mma16816(float& d0, float& d1, float& d2, float& d3,
                                         uint32_t a0, uint32_t a1, uint32_t a2, uint32_t a3,
                                         uint32_t b0, uint32_t b1) {
    asm volatile("mma.sync.aligned.m16n8k16.row.col.f32.f16.f16.f32 "
                 "{%0,%1,%2,%3}, {%4,%5,%6,%7}, {%8,%9}, {%0,%1,%2,%3};"
                 : "+f"(d0), "+f"(d1), "+f"(d2), "+f"(d3)
                 : "r"(a0), "r"(a1), "r"(a2), "r"(a3), "r"(b0), "r"(b1));
}

// smem layout (104704 B -> 2 CTAs/SM)
// Per-warp 8KB AS region: [0..4K) gather table -> Ah tile (32 rows); [4K..8K) Al tile.
// W tiles (Bh/Bl/Wd) staged PER ITERATION into single buffers (CTA-barrier wrapped).
#define SM_AS    0        // 8 x 8192
#define SM_WBH   65536    // 8192 fp16 Bh tile (current iter)
#define SM_WBL   73728    // 8192 fp16 Bl tile
#define SM_WD    81920    // 768 floats packed dot weights
#define SM_LN    84992    // 3 x 192 floats: b_l | ln_g | ln_b
#define SM_FS    87296    // 8 warps x 544 floats transpose buffer [8][68]
#define SM_TOTAL 104704

// ---------------------------------------------------------------------------
__global__ __launch_bounds__(256) void transpose_img_kernel(const float* __restrict__ img) {
    __shared__ float tile[32][65];
    const int r0 = blockIdx.x * 32;
    const int t  = threadIdx.x;
    const int tx = t & 31, ty = t >> 5;
    #pragma unroll
    for (int k = 0; k < 8; ++k) {
        int c = k * 8 + ty;
        tile[tx][c] = img[c * HW + r0 + tx];
    }
    __syncthreads();
    #pragma unroll
    for (int k = 0; k < 8; ++k) {
        int row = k * 4 + (t >> 6);
        int c   = t & 63;
        g_imgTh[(r0 + row) * ED + c] = __float2half(tile[row][c]);
    }
}

// ---------------------------------------------------------------------------
__global__ __launch_bounds__(256, 2) void bev_kernel(
    const float* __restrict__ Tv,     const float* __restrict__ intr,
    const float* __restrict__ bev_in,
    const float* __restrict__ W_off,  const float* __restrict__ b_off,
    const float* __restrict__ s_off,  const float* __restrict__ W_w,
    const float* __restrict__ b_w,
    const float* __restrict__ W_l,    const float* __restrict__ b_l,
    const float* __restrict__ ln_g,   const float* __restrict__ ln_b,
    float* __restrict__ out)
{
    extern __shared__ char smem[];
    const uint32_t smb = smem_u32(smem);
    float* sWd = (float*)(smem + SM_WD);
    float* sLN = (float*)(smem + SM_LN);
    const int t    = threadIdx.x;
    const int warp = t >> 5;
    const int lane = t & 31;
    char* tw   = smem + SM_AS + warp * 8192;            // table / Ah(4K) | Al(4K)
    float* Fsw = (float*)(smem + SM_FS) + warp * 544;   // [8][68]
    const uint32_t asw = smb + SM_AS + warp * 8192;
    const uint32_t wbh = smb + SM_WBH;
    const uint32_t wbl = smb + SM_WBL;

    const int p = blockIdx.x * 256 + t;

    // ---- stage LN params (all 3 iters, once) ----
    for (int idx = t; idx < NITER * 192; idx += 256) {
        int i = idx / 192;
        int r = idx - i * 192;
        int j = r >> 6, e = r & 63;
        float v = (j == 0) ? b_l[i * ED + e] : (j == 1) ? ln_g[i * ED + e] : ln_b[i * ED + e];
        sLN[idx] = v;
    }

    // ---- projected base coords ----
    float pxb, pyb;
    {
        int iz = p & 7;
        int ixy = p >> 3;
        int iy = ixy & 127;
        int ix = ixy >> 7;
        float gx = (float)ix * 0.8f;
        float gy = 51.2f - (float)iy * 0.8f;
        float gz = (float)iz * 0.5f - 2.5f;
        float q0 = Tv[0]*gx + Tv[1]*gy + Tv[2]*gz  + Tv[3];
        float q1 = Tv[4]*gx + Tv[5]*gy + Tv[6]*gz  + Tv[7];
        float q2 = Tv[8]*gx + Tv[9]*gy + Tv[10]*gz + Tv[11];
        float r0 = intr[0]*q0 + intr[1]*q1 + intr[2]*q2;
        float r1 = intr[3]*q0 + intr[4]*q1 + intr[5]*q2;
        float r2 = intr[6]*q0 + intr[7]*q1 + intr[8]*q2;
        float invz = 1.0f / r2;
        float cx = r0 * invz * (1.0f / 640.0f) - 1.0f;
        float cy = r1 * invz * (1.0f / 192.0f) - 1.0f;
        pxb = cx * 160.0f + 159.5f;
        pyb = cy * 48.0f  + 47.5f;
    }

    // ---- load B state into registers (smem transpose, 8-row groups) ----
    ull bb[32];
    const int pwarp0 = blockIdx.x * 256 + warp * 32;
    #pragma unroll
    for (int g = 0; g < 4; ++g) {
        #pragma unroll
        for (int q = 0; q < 8; ++q) {
            int pt = pwarp0 + g * 8 + q;
            ull v = *((const ull*)(bev_in + (size_t)pt * ED) + lane);
            *(ull*)&Fsw[q * 68 + 2 * lane] = v;
        }
        __syncwarp();
        if ((lane >> 3) == g) {
            #pragma unroll
            for (int q = 0; q < 32; ++q)
                bb[q] = *(ull*)&Fsw[(lane & 7) * 68 + 2 * q];
        }
        __syncwarp();
    }

    for (int i = 0; i < NITER; ++i) {
        // ===== stage this iteration's weights (CTA-wide, barrier-wrapped) =====
        __syncthreads();   // prior iter's ldsm reads of WBH/WBL complete
        {
            const float* Wsrc = W_l + i * 4096;
            #pragma unroll
            for (int u = 0; u < 16; ++u) {
                int idx = t + u * 256;
                int e = idx >> 6, c = idx & 63;
                float w = Wsrc[idx];
                __half h = __float2half(w);
                __half l = __float2half(w - __half2float(h));
                uint32_t off = SWZ((uint32_t)(e * 128 + c * 2));
                *(__half*)(smem + SM_WBH + off) = h;
                *(__half*)(smem + SM_WBL + off) = l;
            }
            #pragma unroll
            for (int u = 0; u < 3; ++u) {
                int idx = t + u * 256;
                int e = idx / 12, j = idx - e * 12;
                float v = 0.0f;
                if (j < 6)      v = W_off[i * 384 + e * 6 + j];
                else if (j < 9) v = W_w[i * 192 + e * 3 + (j - 6)];
                sWd[idx] = v;
            }
        }
        __syncthreads();

        const float* sLN_i = sLN + i * 192;

        // ===== dots: 10 logits, broadcast weight rows =====
        float d[10];
        {
            ull acc[5] = {0, 0, 0, 0, 0};
            #pragma unroll
            for (int ep = 0; ep < 32; ++ep) {
                float be0, be1; unpk(bb[ep], be0, be1);
                ull bs0 = splat(be0), bs1 = splat(be1);
                const ulonglong2* w0 = (const ulonglong2*)&sWd[(2 * ep) * 12];
                const ulonglong2* w1 = (const ulonglong2*)&sWd[(2 * ep + 1) * 12];
                ulonglong2 wa = w0[0], wb = w0[1], wc = w0[2];
                acc[0] = fma2(bs0, wa.x, acc[0]); acc[1] = fma2(bs0, wa.y, acc[1]);
                acc[2] = fma2(bs0, wb.x, acc[2]); acc[3] = fma2(bs0, wb.y, acc[3]);
                acc[4] = fma2(bs0, wc.x, acc[4]);
                wa = w1[0]; wb = w1[1]; wc = w1[2];
                acc[0] = fma2(bs1, wa.x, acc[0]); acc[1] = fma2(bs1, wa.y, acc[1]);
                acc[2] = fma2(bs1, wb.x, acc[2]); acc[3] = fma2(bs1, wb.y, acc[3]);
                acc[4] = fma2(bs1, wc.x, acc[4]);
            }
            #pragma unroll
            for (int q = 0; q < 5; ++q) unpk(acc[q], d[2 * q], d[2 * q + 1]);
        }

        // ===== G1: offsets/softmax -> gather table (SWZ rows in AS region) =====
        {
            const float sc = __ldg(s_off + i);
            float off[6];
            #pragma unroll
            for (int j = 0; j < 6; ++j) off[j] = (d[j] + __ldg(b_off + i * 6 + j)) * sc;
            float l0 = d[6] + __ldg(b_w + i * 3 + 0);
            float l1 = d[7] + __ldg(b_w + i * 3 + 1);
            float l2 = d[8] + __ldg(b_w + i * 3 + 2);
            float mx = fmaxf(l0, fmaxf(l1, l2));
            float e0 = __expf(l0 - mx), e1 = __expf(l1 - mx), e2 = __expf(l2 - mx);
            float inv = 1.0f / (e0 + e1 + e2);
            float wk[3] = {e0 * inv, e1 * inv, e2 * inv};
            #pragma unroll
            for (int k = 0; k < 3; ++k) {
                float px = fmaf(off[2 * k],     160.0f, pxb);
                float py = fmaf(off[2 * k + 1],  48.0f, pyb);
                float fx = floorf(px), fy = floorf(py);
                int x0 = (int)fx, y0 = (int)fy;
                float wx1 = px - fx, wy1 = py - fy;
                float wx0 = 1.0f - wx1, wy0 = 1.0f - wy1;
                bool vx0 = (unsigned)x0 < (unsigned)FWD, vx1 = (unsigned)(x0 + 1) < (unsigned)FWD;
                bool vy0 = (unsigned)y0 < (unsigned)FHD, vy1 = (unsigned)(y0 + 1) < (unsigned)FHD;
                int xc0 = min(max(x0, 0), FWD - 1), xc1 = min(max(x0 + 1, 0), FWD - 1);
                int yc0 = min(max(y0, 0), FHD - 1), yc1 = min(max(y0 + 1, 0), FHD - 1);
                int rA = yc0 * FWD, rB = yc1 * FWD;
                float W = wk[k];
                float w00 = (vx0 && vy0) ? W * wx0 * wy0 : 0.0f;
                float w01 = (vx1 && vy0) ? W * wx1 * wy0 : 0.0f;
                float w10 = (vx0 && vy1) ? W * wx0 * wy1 : 0.0f;
                float w11 = (vx1 && vy1) ? W * wx1 * wy1 : 0.0f;
                *(float4*)(tw + SWZ((uint32_t)(lane * 128 + k * 32))) = make_float4(
                    __int_as_float((rA + xc0) << 6), __int_as_float((rA + xc1) << 6),
                    __int_as_float((rB + xc0) << 6), __int_as_float((rB + xc1) << 6));
                *(float4*)(tw + SWZ((uint32_t)(lane * 128 + k * 32 + 16))) =
                    make_float4(w00, w01, w10, w11);
            }
        }
        __syncwarp();

        // ===== G2: half-warp-per-point gather (fp16 image), split acc chains =====
        {
            const int half16 = lane >> 4;
            const int li     = lane & 15;
            #pragma unroll 1
            for (int g = 0; g < 4; ++g) {
                #pragma unroll 2
                for (int qq = 0; qq < 4; ++qq) {
                    const int pt = g * 8 + qq * 2 + half16;
                    ull accA0 = 0, accA1 = 0, accB0 = 0, accB1 = 0;
                    #pragma unroll
                    for (int k = 0; k < 3; ++k) {
                        float4 A  = *(const float4*)(tw + SWZ((uint32_t)(pt * 128 + k * 32)));
                        float4 Wt = *(const float4*)(tw + SWZ((uint32_t)(pt * 128 + k * 32 + 16)));
                        #pragma unroll
                        for (int c = 0; c < 4; ++c) {
                            int   base = __float_as_int(c == 0 ? A.x : c == 1 ? A.y : c == 2 ? A.z : A.w);
                            float wgt  =                (c == 0 ? Wt.x : c == 1 ? Wt.y : c == 2 ? Wt.z : Wt.w);
                            uint2 raw = *(const uint2*)(g_imgTh + base + 4 * li);
                            float2 v0 = __half22float2(*(__half2*)&raw.x);
                            float2 v1 = __half22float2(*(__half2*)&raw.y);
                            ull ws = splat(wgt);
                            if (k == 1) {
                                accB0 = fma2(ws, pk2(v0.x, v0.y), accB0);
                                accB1 = fma2(ws, pk2(v1.x, v1.y), accB1);
                            } else {
                                accA0 = fma2(ws, pk2(v0.x, v0.y), accA0);
                                accA1 = fma2(ws, pk2(v1.x, v1.y), accA1);
                            }
                        }
                    }
                    ull acc0 = add2(accA0, accB0);
                    ull acc1 = add2(accA1, accB1);
                    float a0, a1, a2, a3;
                    unpk(acc0, a0, a1); unpk(acc1, a2, a3);
                    *(float4*)&Fsw[(qq * 2 + half16) * 68 + 4 * li] =
                        make_float4(a0, a1, a2, a3);
                }
                __syncwarp();
                if ((lane >> 3) == g) {
                    #pragma unroll
                    for (int q = 0; q < 32; ++q)
                        bb[q] = add2(bb[q], *(ull*)&Fsw[(lane & 7) * 68 + 2 * q]);
                }
                __syncwarp();
            }
        }

        // ===== write FULL Ah|Al tiles (32 rows, all lanes, single pass) =====
        {
            #pragma unroll
            for (int cb = 0; cb < 8; ++cb) {
                uint32_t hv[4], lv[4];
                #pragma unroll
                for (int j = 0; j < 4; ++j) {
                    float a, b; unpk(bb[4 * cb + j], a, b);
                    __half2 hh = __floats2half2_rn(a, b);
                    float2 bk = __half22float2(hh);
                    __half2 ll = __floats2half2_rn(a - bk.x, b - bk.y);
                    hv[j] = *(uint32_t*)&hh;
                    lv[j] = *(uint32_t*)&ll;
                }
                uint32_t off = SWZ((uint32_t)(lane * 128 + cb * 16));
                *(uint4*)(tw + off)        = make_uint4(hv[0], hv[1], hv[2], hv[3]);
                *(uint4*)(tw + 4096 + off) = make_uint4(lv[0], lv[1], lv[2], lv[3]);
            }
        }
        __syncwarp();

        // ===== matvec via split-precision mma.sync, two m16 halves =====
        const int qr = lane >> 2;
        const int qc = (lane & 3) * 2;
        #pragma unroll
        for (int mt = 0; mt < 2; ++mt) {
            float D[8][4];
            #pragma unroll
            for (int nt = 0; nt < 8; ++nt) {
                float2 bv = *(const float2*)&sLN_i[nt * 8 + qc];
                D[nt][0] = bv.x; D[nt][1] = bv.y;
                D[nt][2] = bv.x; D[nt][3] = bv.y;
            }
            const uint32_t arow = (uint32_t)(mt * 16 + (lane & 15));
            const uint32_t koff8 = (uint32_t)(((lane >> 4) & 1) << 3);
            #pragma unroll
            for (int kt = 0; kt < 4; ++kt) {
                uint32_t ah0, ah1, ah2, ah3, al0, al1, al2, al3;
                uint32_t aoff = SWZ(arow * 128 + (kt * 16 + koff8) * 2);
                ldsm_x4(ah0, ah1, ah2, ah3, asw + aoff);
                ldsm_x4(al0, al1, al2, al3, asw + 4096 + aoff);
                const uint32_t brow = (uint32_t)(kt * 16 + (lane & 15));
                #pragma unroll
                for (int np = 0; np < 4; ++np) {
                    uint32_t boff = SWZ(brow * 128 + (np * 16 + koff8) * 2);
                    uint32_t bh0, bh1, bh2, bh3, bl0, bl1, bl2, bl3;
                    ldsm_x4t(bh0, bh1, bh2, bh3, wbh + boff);
                    ldsm_x4t(bl0, bl1, bl2, bl3, wbl + boff);
                    mma16816(D[2*np][0],   D[2*np][1],   D[2*np][2],   D[2*np][3],
                             ah0, ah1, ah2, ah3, bh0, bh1);
                    mma16816(D[2*np+1][0], D[2*np+1][1], D[2*np+1][2], D[2*np+1][3],
                             ah0, ah1, ah2, ah3, bh2, bh3);
                    mma16816(D[2*np][0],   D[2*np][1],   D[2*np][2],   D[2*np][3],
                             al0, al1, al2, al3, bh0, bh1);
                    mma16816(D[2*np+1][0], D[2*np+1][1], D[2*np+1][2], D[2*np+1][3],
                             al0, al1, al2, al3, bh2, bh3);
                    mma16816(D[2*np][0],   D[2*np][1],   D[2*np][2],   D[2*np][3],
                             ah0, ah1, ah2, ah3, bl0, bl1);
                    mma16816(D[2*np+1][0], D[2*np+1][1], D[2*np+1][2], D[2*np+1][3],
                             ah0, ah1, ah2, ah3, bl2, bl3);
                }
            }
            float s1a = 0.f, s2a = 0.f, s1b = 0.f, s2b = 0.f;
            #pragma unroll
            for (int nt = 0; nt < 8; ++nt) {
                s1a += D[nt][0] + D[nt][1];
                s2a = fmaf(D[nt][0], D[nt][0], s2a); s2a = fmaf(D[nt][1], D[nt][1], s2a);
                s1b += D[nt][2] + D[nt][3];
                s2b = fmaf(D[nt][2], D[nt][2], s2b); s2b = fmaf(D[nt][3], D[nt][3], s2b);
            }
            #pragma unroll
            for (int o = 1; o < 4; o <<= 1) {
                s1a += __shfl_xor_sync(0xffffffffu, s1a, o);
                s2a += __shfl_xor_sync(0xffffffffu, s2a, o);
                s1b += __shfl_xor_sync(0xffffffffu, s1b, o);
                s2b += __shfl_xor_sync(0xffffffffu, s2b, o);
            }
            float muA = s1a * (1.0f / ED);
            float rsA = rsqrtf(s2a * (1.0f / ED) - muA * muA + 1e-5f);
            float muB = s1b * (1.0f / ED);
            float rsB = rsqrtf(s2b * (1.0f / ED) - muB * muB + 1e-5f);

            #pragma unroll
            for (int nt = 0; nt < 8; ++nt) {
                int c = nt * 8 + qc;
                float2 gv = *(const float2*)&sLN_i[64 + c];
                float2 bv = *(const float2*)&sLN_i[128 + c];
                float r0 = fmaf((D[nt][0] - muA) * rsA, gv.x, bv.x);
                float r1 = fmaf((D[nt][1] - muA) * rsA, gv.y, bv.y);
                *(float2*)&Fsw[qr * 68 + c] = make_float2(r0, r1);
            }
            __syncwarp();
            if ((lane >> 3) == mt * 2) {
                #pragma unroll
                for (int q = 0; q < 32; ++q)
                    bb[q] = add2(bb[q], *(ull*)&Fsw[(lane & 7) * 68 + 2 * q]);
            }
            __syncwarp();
            #pragma unroll
            for (int nt = 0; nt < 8; ++nt) {
                int c = nt * 8 + qc;
                float2 gv = *(const float2*)&sLN_i[64 + c];
                float2 bv = *(const float2*)&sLN_i[128 + c];
                float r2 = fmaf((D[nt][2] - muB) * rsB, gv.x, bv.x);
                float r3 = fmaf((D[nt][3] - muB) * rsB, gv.y, bv.y);
                *(float2*)&Fsw[qr * 68 + c] = make_float2(r2, r3);
            }
            __syncwarp();
            if ((lane >> 3) == mt * 2 + 1) {
                #pragma unroll
                for (int q = 0; q < 32; ++q)
                    bb[q] = add2(bb[q], *(ull*)&Fsw[(lane & 7) * 68 + 2 * q]);
            }
            __syncwarp();
        }
    }

    // ===== epilogue: z-mean over 8-lane groups =====
    {
        int cell = p >> 3;
        int iy = cell & 127;
        int ix = cell >> 7;
        int cidx = iy * XD + ix;
        bool writer = (lane & 7) == 0;
        #pragma unroll
        for (int q = 0; q < 32; ++q) {
            float a, b; unpk(bb[q], a, b);
            #pragma unroll
            for (int o = 1; o < 8; o <<= 1) {
                a += __shfl_xor_sync(0xffffffffu, a, o);
                b += __shfl_xor_sync(0xffffffffu, b, o);
            }
            if (writer) {
                out[(2 * q)     * (XD * YD) + cidx] = a * 0.125f;
                out[(2 * q + 1) * (XD * YD) + cidx] = b * 0.125f;
            }
        }
    }
}

// ---------------------------------------------------------------------------
extern "C" void kernel_launch(void* const* d_in, const int* in_sizes, int n_in,
                              void* d_out, int out_size) {
    const float* Tv     = (const float*)d_in[0];
    const float* intr   = (const float*)d_in[1];
    const float* img    = (const float*)d_in[2];
    const float* bev_in = (const float*)d_in[3];
    const float* W_off  = (const float*)d_in[4];
    const float* b_off  = (const float*)d_in[5];
    const float* s_off  = (const float*)d_in[6];
    const float* W_w    = (const float*)d_in[7];
    const float* b_w    = (const float*)d_in[8];
    const float* W_l    = (const float*)d_in[9];
    const float* b_l    = (const float*)d_in[10];
    const float* ln_g   = (const float*)d_in[11];
    const float* ln_b   = (const float*)d_in[12];
    float* out = (float*)d_out;

    cudaFuncSetAttribute(bev_kernel, cudaFuncAttributeMaxDynamicSharedMemorySize, SM_TOTAL);

    transpose_img_kernel<<<HW / 32, 256>>>(img);
    bev_kernel<<<NPTS / 256, 256, SM_TOTAL>>>(Tv, intr, bev_in,
                                              W_off, b_off, s_off, W_w, b_w,
                                              W_l, b_l, ln_g, ln_b, out);
}

// round 13
// speedup vs baseline: 1.0192x; 1.0192x over previous
#include <cuda_runtime.h>
#include <cuda_fp16.h>
#include <cstdint>

#define XD 128
#define YD 128
#define ZD 8
#define ED 64
#define NITER 3
#define FHD 96
#define FWD 320
#define NPTS (XD*YD*ZD)
#define HW (FHD*FWD)

typedef unsigned long long ull;

__device__ __half g_imgTh[HW * ED];   // (H,W,C) fp16 image, 3.9 MB

__device__ __forceinline__ ull pk2(float x, float y) {
    ull r; asm("mov.b64 %0,{%1,%2};" : "=l"(r) : "f"(x), "f"(y)); return r;
}
__device__ __forceinline__ ull splat(float x) { return pk2(x, x); }
__device__ __forceinline__ void unpk(ull v, float& x, float& y) {
    asm("mov.b64 {%0,%1},%2;" : "=f"(x), "=f"(y) : "l"(v));
}
__device__ __forceinline__ ull fma2(ull a, ull b, ull c) {
    ull d; asm("fma.rn.f32x2 %0,%1,%2,%3;" : "=l"(d) : "l"(a), "l"(b), "l"(c)); return d;
}
__device__ __forceinline__ ull add2(ull a, ull b) {
    ull d; asm("add.rn.f32x2 %0,%1,%2;" : "=l"(d) : "l"(a), "l"(b)); return d;
}
__device__ __forceinline__ uint32_t smem_u32(const void* p) {
    uint32_t a; asm("{ .reg .u64 t; cvta.to.shared.u64 t, %1; cvt.u32.u64 %0, t; }" : "=r"(a) : "l"(p));
    return a;
}

#define SWZ(off) ((off) ^ (((off) >> 3) & 0x70))

__device__ __forceinline__ void ldsm_x4(uint32_t& r0, uint32_t& r1, uint32_t& r2, uint32_t& r3,
                                        uint32_t addr) {
    asm volatile("ldmatrix.sync.aligned.m8n8.x4.shared.b16 {%0,%1,%2,%3}, [%4];"
                 : "=r"(r0), "=r"(r1), "=r"(r2), "=r"(r3) : "r"(addr));
}
__device__ __forceinline__ void ldsm_x4t(uint32_t& r0, uint32_t& r1, uint32_t& r2, uint32_t& r3,
                                         uint32_t addr) {
    asm volatile("ldmatrix.sync.aligned.m8n8.x4.trans.shared.b16 {%0,%1,%2,%3}, [%4];"
                 : "=r"(r0), "=r"(r1), "=r"(r2), "=r"(r3) : "r"(addr));
}
__device__ __forceinline__ void mma16816(float& d0, float& d1, float& d2, float& d3,
                                         uint32_t a0, uint32_t a1, uint32_t a2, uint32_t a3,
                                         uint32_t b0, uint32_t b1) {
    asm volatile("mma.sync.aligned.m16n8k16.row.col.f32.f16.f16.f32 "
                 "{%0,%1,%2,%3}, {%4,%5,%6,%7}, {%8,%9}, {%0,%1,%2,%3};"
                 : "+f"(d0), "+f"(d1), "+f"(d2), "+f"(d3)
                 : "r"(a0), "r"(a1), "r"(a2), "r"(a3), "r"(b0), "r"(b1));
}

// smem byte layout (110848 B -> 2 CTAs/SM)
#define SM_AS    0        // 8 x 4096: gather table, then Ah|Al half-tiles
#define SM_WBH   32768    // 3 x 8192 fp16 Bh tiles (rows e, SW128)
#define SM_WBL   57344    // 3 x 8192 fp16 Bl tiles (residual)
#define SM_WD    81920    // 3 x 768 floats packed dot weights
#define SM_LN    91136    // 3 x 192 floats: b_l | ln_g | ln_b
#define SM_FS    93440    // 8 warps x 544 floats transpose buffer [8][68]
#define SM_TOTAL 110848

// ---------------------------------------------------------------------------
__global__ __launch_bounds__(256) void transpose_img_kernel(const float* __restrict__ img) {
    __shared__ float tile[32][65];
    const int r0 = blockIdx.x * 32;
    const int t  = threadIdx.x;
    const int tx = t & 31, ty = t >> 5;
    #pragma unroll
    for (int k = 0; k < 8; ++k) {
        int c = k * 8 + ty;
        tile[tx][c] = img[c * HW + r0 + tx];
    }
    __syncthreads();
    #pragma unroll
    for (int k = 0; k < 8; ++k) {
        int row = k * 4 + (t >> 6);
        int c   = t & 63;
        g_imgTh[(r0 + row) * ED + c] = __float2half(tile[row][c]);
    }
}

// ---------------------------------------------------------------------------
__global__ __launch_bounds__(256, 2) void bev_kernel(
    const float* __restrict__ Tv,     const float* __restrict__ intr,
    const float* __restrict__ bev_in,
    const float* __restrict__ W_off,  const float* __restrict__ b_off,
    const float* __restrict__ s_off,  const float* __restrict__ W_w,
    const float* __restrict__ b_w,
    const float* __restrict__ W_l,    const float* __restrict__ b_l,
    const float* __restrict__ ln_g,   const float* __restrict__ ln_b,
    float* __restrict__ out)
{
    extern __shared__ char smem[];
    const uint32_t smb = smem_u32(smem);
    float* sWd = (float*)(smem + SM_WD);
    float* sLN = (float*)(smem + SM_LN);
    const int t    = threadIdx.x;
    const int warp = t >> 5;
    const int lane = t & 31;
    char* tw   = smem + SM_AS + warp * 4096;            // table / Ah|Al half-tiles
    float* Fsw = (float*)(smem + SM_FS) + warp * 544;   // [8][68]
    const uint32_t asw = smb + SM_AS + warp * 4096;

    const int p = blockIdx.x * 256 + t;

    // ---- stage W_l as split fp16 SW128 tiles Bh / Bl ----
    for (int idx = t; idx < NITER * 4096; idx += 256) {
        int i = idx >> 12;
        int r = idx & 4095;
        int e = r >> 6, c = r & 63;
        float w = W_l[idx];
        __half h = __float2half(w);
        __half l = __float2half(w - __half2float(h));
        uint32_t off = SWZ((uint32_t)(e * 128 + c * 2));
        *(__half*)(smem + SM_WBH + i * 8192 + off) = h;
        *(__half*)(smem + SM_WBL + i * 8192 + off) = l;
    }
    // ---- stage packed dot weights ----
    #pragma unroll
    for (int u = 0; u < 9; ++u) {
        int idx = t + u * 256;
        int i = idx / 768;
        int r = idx - i * 768;
        int e = r / 12, j = r - e * 12;
        float v = 0.0f;
        if (j < 6)      v = W_off[i * 384 + e * 6 + j];
        else if (j < 9) v = W_w[i * 192 + e * 3 + (j - 6)];
        sWd[idx] = v;
    }
    // ---- stage LN params ----
    for (int idx = t; idx < NITER * 192; idx += 256) {
        int i = idx / 192;
        int r = idx - i * 192;
        int j = r >> 6, e = r & 63;
        float v = (j == 0) ? b_l[i * ED + e] : (j == 1) ? ln_g[i * ED + e] : ln_b[i * ED + e];
        sLN[idx] = v;
    }

    // ---- projected base coords ----
    float pxb, pyb;
    {
        int iz = p & 7;
        int ixy = p >> 3;
        int iy = ixy & 127;
        int ix = ixy >> 7;
        float gx = (float)ix * 0.8f;
        float gy = 51.2f - (float)iy * 0.8f;
        float gz = (float)iz * 0.5f - 2.5f;
        float q0 = Tv[0]*gx + Tv[1]*gy + Tv[2]*gz  + Tv[3];
        float q1 = Tv[4]*gx + Tv[5]*gy + Tv[6]*gz  + Tv[7];
        float q2 = Tv[8]*gx + Tv[9]*gy + Tv[10]*gz + Tv[11];
        float r0 = intr[0]*q0 + intr[1]*q1 + intr[2]*q2;
        float r1 = intr[3]*q0 + intr[4]*q1 + intr[5]*q2;
        float r2 = intr[6]*q0 + intr[7]*q1 + intr[8]*q2;
        float invz = 1.0f / r2;
        float cx = r0 * invz * (1.0f / 640.0f) - 1.0f;
        float cy = r1 * invz * (1.0f / 192.0f) - 1.0f;
        pxb = cx * 160.0f + 159.5f;
        pyb = cy * 48.0f  + 47.5f;
    }

    // ---- load B state into registers (smem transpose, 8-row groups) ----
    ull bb[32];
    const int pwarp0 = blockIdx.x * 256 + warp * 32;
    #pragma unroll
    for (int g = 0; g < 4; ++g) {
        #pragma unroll
        for (int q = 0; q < 8; ++q) {
            int pt = pwarp0 + g * 8 + q;
            ull v = *((const ull*)(bev_in + (size_t)pt * ED) + lane);
            *(ull*)&Fsw[q * 68 + 2 * lane] = v;
        }
        __syncwarp();
        if ((lane >> 3) == g) {
            #pragma unroll
            for (int q = 0; q < 32; ++q)
                bb[q] = *(ull*)&Fsw[(lane & 7) * 68 + 2 * q];
        }
        __syncwarp();
    }

    __syncthreads();   // weights staged

    for (int i = 0; i < NITER; ++i) {
        const float* sWd_i = sWd + i * 768;
        const float* sLN_i = sLN + i * 192;
        const uint32_t wbh_i = smb + SM_WBH + i * 8192;
        const uint32_t wbl_i = smb + SM_WBL + i * 8192;

        // ===== dots: 10 logits, broadcast weight rows =====
        float d[10];
        {
            ull acc[5] = {0, 0, 0, 0, 0};
            #pragma unroll
            for (int ep = 0; ep < 32; ++ep) {
                float be0, be1; unpk(bb[ep], be0, be1);
                ull bs0 = splat(be0), bs1 = splat(be1);
                const ulonglong2* w0 = (const ulonglong2*)&sWd_i[(2 * ep) * 12];
                const ulonglong2* w1 = (const ulonglong2*)&sWd_i[(2 * ep + 1) * 12];
                ulonglong2 wa = w0[0], wb = w0[1], wc = w0[2];
                acc[0] = fma2(bs0, wa.x, acc[0]); acc[1] = fma2(bs0, wa.y, acc[1]);
                acc[2] = fma2(bs0, wb.x, acc[2]); acc[3] = fma2(bs0, wb.y, acc[3]);
                acc[4] = fma2(bs0, wc.x, acc[4]);
                wa = w1[0]; wb = w1[1]; wc = w1[2];
                acc[0] = fma2(bs1, wa.x, acc[0]); acc[1] = fma2(bs1, wa.y, acc[1]);
                acc[2] = fma2(bs1, wb.x, acc[2]); acc[3] = fma2(bs1, wb.y, acc[3]);
                acc[4] = fma2(bs1, wc.x, acc[4]);
            }
            #pragma unroll
            for (int q = 0; q < 5; ++q) unpk(acc[q], d[2 * q], d[2 * q + 1]);
        }

        // ===== G1: offsets/softmax -> gather table (SWZ rows) =====
        {
            const float sc = __ldg(s_off + i);
            float off[6];
            #pragma unroll
            for (int j = 0; j < 6; ++j) off[j] = (d[j] + __ldg(b_off + i * 6 + j)) * sc;
            float l0 = d[6] + __ldg(b_w + i * 3 + 0);
            float l1 = d[7] + __ldg(b_w + i * 3 + 1);
            float l2 = d[8] + __ldg(b_w + i * 3 + 2);
            float mx = fmaxf(l0, fmaxf(l1, l2));
            float e0 = __expf(l0 - mx), e1 = __expf(l1 - mx), e2 = __expf(l2 - mx);
            float inv = 1.0f / (e0 + e1 + e2);
            float wk[3] = {e0 * inv, e1 * inv, e2 * inv};
            #pragma unroll
            for (int k = 0; k < 3; ++k) {
                float px = fmaf(off[2 * k],     160.0f, pxb);
                float py = fmaf(off[2 * k + 1],  48.0f, pyb);
                float fx = floorf(px), fy = floorf(py);
                int x0 = (int)fx, y0 = (int)fy;
                float wx1 = px - fx, wy1 = py - fy;
                float wx0 = 1.0f - wx1, wy0 = 1.0f - wy1;
                bool vx0 = (unsigned)x0 < (unsigned)FWD, vx1 = (unsigned)(x0 + 1) < (unsigned)FWD;
                bool vy0 = (unsigned)y0 < (unsigned)FHD, vy1 = (unsigned)(y0 + 1) < (unsigned)FHD;
                int xc0 = min(max(x0, 0), FWD - 1), xc1 = min(max(x0 + 1, 0), FWD - 1);
                int yc0 = min(max(y0, 0), FHD - 1), yc1 = min(max(y0 + 1, 0), FHD - 1);
                int rA = yc0 * FWD, rB = yc1 * FWD;
                float W = wk[k];
                float w00 = (vx0 && vy0) ? W * wx0 * wy0 : 0.0f;
                float w01 = (vx1 && vy0) ? W * wx1 * wy0 : 0.0f;
                float w10 = (vx0 && vy1) ? W * wx0 * wy1 : 0.0f;
                float w11 = (vx1 && vy1) ? W * wx1 * wy1 : 0.0f;
                *(float4*)(tw + SWZ((uint32_t)(lane * 128 + k * 32))) = make_float4(
                    __int_as_float((rA + xc0) << 6), __int_as_float((rA + xc1) << 6),
                    __int_as_float((rB + xc0) << 6), __int_as_float((rB + xc1) << 6));
                *(float4*)(tw + SWZ((uint32_t)(lane * 128 + k * 32 + 16))) =
                    make_float4(w00, w01, w10, w11);
            }
        }
        __syncwarp();

        // ===== G2: half-warp-per-point gather (fp16 image), split chains =====
        {
            const int half16 = lane >> 4;
            const int li     = lane & 15;
            #pragma unroll 1
            for (int g = 0; g < 4; ++g) {
                #pragma unroll 2
                for (int qq = 0; qq < 4; ++qq) {
                    const int pt = g * 8 + qq * 2 + half16;
                    // hoist table reads for all 3 samples
                    float4 A0  = *(const float4*)(tw + SWZ((uint32_t)(pt * 128 + 0)));
                    float4 W0  = *(const float4*)(tw + SWZ((uint32_t)(pt * 128 + 16)));
                    float4 A1  = *(const float4*)(tw + SWZ((uint32_t)(pt * 128 + 32)));
                    float4 W1  = *(const float4*)(tw + SWZ((uint32_t)(pt * 128 + 48)));
                    float4 A2  = *(const float4*)(tw + SWZ((uint32_t)(pt * 128 + 64)));
                    float4 W2  = *(const float4*)(tw + SWZ((uint32_t)(pt * 128 + 80)));
                    ull accA0 = 0, accA1 = 0, accB0 = 0, accB1 = 0;
                    #pragma unroll
                    for (int k = 0; k < 3; ++k) {
                        float4 A  = (k == 0) ? A0 : (k == 1) ? A1 : A2;
                        float4 Wt = (k == 0) ? W0 : (k == 1) ? W1 : W2;
                        #pragma unroll
                        for (int c = 0; c < 4; ++c) {
                            int   base = __float_as_int(c == 0 ? A.x : c == 1 ? A.y : c == 2 ? A.z : A.w);
                            float wgt  =                (c == 0 ? Wt.x : c == 1 ? Wt.y : c == 2 ? Wt.z : Wt.w);
                            uint2 raw = *(const uint2*)(g_imgTh + base + 4 * li);
                            float2 v0 = __half22float2(*(__half2*)&raw.x);
                            float2 v1 = __half22float2(*(__half2*)&raw.y);
                            ull ws = splat(wgt);
                            if (k == 1) {
                                accB0 = fma2(ws, pk2(v0.x, v0.y), accB0);
                                accB1 = fma2(ws, pk2(v1.x, v1.y), accB1);
                            } else {
                                accA0 = fma2(ws, pk2(v0.x, v0.y), accA0);
                                accA1 = fma2(ws, pk2(v1.x, v1.y), accA1);
                            }
                        }
                    }
                    ull acc0 = add2(accA0, accB0);
                    ull acc1 = add2(accA1, accB1);
                    float a0, a1, a2, a3;
                    unpk(acc0, a0, a1); unpk(acc1, a2, a3);
                    *(float4*)&Fsw[(qq * 2 + half16) * 68 + 4 * li] =
                        make_float4(a0, a1, a2, a3);
                }
                __syncwarp();
                if ((lane >> 3) == g) {
                    #pragma unroll
                    for (int q = 0; q < 32; ++q)
                        bb[q] = add2(bb[q], *(ull*)&Fsw[(lane & 7) * 68 + 2 * q]);
                }
                __syncwarp();
            }
        }

        // ===== matvec via split-precision mma.sync, two m16 halves =====
        const int qr = lane >> 2;
        const int qc = (lane & 3) * 2;
        #pragma unroll
        for (int mt = 0; mt < 2; ++mt) {
            if ((lane >> 4) == mt) {
                int row = lane & 15;
                #pragma unroll
                for (int cb = 0; cb < 8; ++cb) {
                    uint32_t hv[4], lv[4];
                    #pragma unroll
                    for (int j = 0; j < 4; ++j) {
                        float a, b; unpk(bb[4 * cb + j], a, b);
                        __half2 hh = __floats2half2_rn(a, b);
                        float2 bk = __half22float2(hh);
                        __half2 ll = __floats2half2_rn(a - bk.x, b - bk.y);
                        hv[j] = *(uint32_t*)&hh;
                        lv[j] = *(uint32_t*)&ll;
                    }
                    uint32_t off = SWZ((uint32_t)(row * 128 + cb * 16));
                    *(uint4*)(tw + off)        = make_uint4(hv[0], hv[1], hv[2], hv[3]);
                    *(uint4*)(tw + 2048 + off) = make_uint4(lv[0], lv[1], lv[2], lv[3]);
                }
            }
            __syncwarp();

            float D[8][4];
            #pragma unroll
            for (int nt = 0; nt < 8; ++nt) {
                float2 bv = *(const float2*)&sLN_i[nt * 8 + qc];
                D[nt][0] = bv.x; D[nt][1] = bv.y;
                D[nt][2] = bv.x; D[nt][3] = bv.y;
            }
            const uint32_t arow = (uint32_t)(lane & 15);
            const uint32_t koff8 = (uint32_t)(((lane >> 4) & 1) << 3);
            #pragma unroll
            for (int kt = 0; kt < 4; ++kt) {
                uint32_t ah0, ah1, ah2, ah3, al0, al1, al2, al3;
                uint32_t aoff = SWZ(arow * 128 + (kt * 16 + koff8) * 2);
                ldsm_x4(ah0, ah1, ah2, ah3, asw + aoff);
                ldsm_x4(al0, al1, al2, al3, asw + 2048 + aoff);
                const uint32_t brow = (uint32_t)(kt * 16 + (lane & 15));
                #pragma unroll
                for (int np = 0; np < 4; ++np) {
                    uint32_t boff = SWZ(brow * 128 + (np * 16 + koff8) * 2);
                    uint32_t bh0, bh1, bh2, bh3, bl0, bl1, bl2, bl3;
                    ldsm_x4t(bh0, bh1, bh2, bh3, wbh_i + boff);
                    ldsm_x4t(bl0, bl1, bl2, bl3, wbl_i + boff);
                    mma16816(D[2*np][0],   D[2*np][1],   D[2*np][2],   D[2*np][3],
                             ah0, ah1, ah2, ah3, bh0, bh1);
                    mma16816(D[2*np+1][0], D[2*np+1][1], D[2*np+1][2], D[2*np+1][3],
                             ah0, ah1, ah2, ah3, bh2, bh3);
                    mma16816(D[2*np][0],   D[2*np][1],   D[2*np][2],   D[2*np][3],
                             al0, al1, al2, al3, bh0, bh1);
                    mma16816(D[2*np+1][0], D[2*np+1][1], D[2*np+1][2], D[2*np+1][3],
                             al0, al1, al2, al3, bh2, bh3);
                    mma16816(D[2*np][0],   D[2*np][1],   D[2*np][2],   D[2*np][3],
                             ah0, ah1, ah2, ah3, bl0, bl1);
                    mma16816(D[2*np+1][0], D[2*np+1][1], D[2*np+1][2], D[2*np+1][3],
                             ah0, ah1, ah2, ah3, bl2, bl3);
                }
            }
            float s1a = 0.f, s2a = 0.f, s1b = 0.f, s2b = 0.f;
            #pragma unroll
            for (int nt = 0; nt < 8; ++nt) {
                s1a += D[nt][0] + D[nt][1];
                s2a = fmaf(D[nt][0], D[nt][0], s2a); s2a = fmaf(D[nt][1], D[nt][1], s2a);
                s1b += D[nt][2] + D[nt][3];
                s2b = fmaf(D[nt][2], D[nt][2], s2b); s2b = fmaf(D[nt][3], D[nt][3], s2b);
            }
            #pragma unroll
            for (int o = 1; o < 4; o <<= 1) {
                s1a += __shfl_xor_sync(0xffffffffu, s1a, o);
                s2a += __shfl_xor_sync(0xffffffffu, s2a, o);
                s1b += __shfl_xor_sync(0xffffffffu, s1b, o);
                s2b += __shfl_xor_sync(0xffffffffu, s2b, o);
            }
            float muA = s1a * (1.0f / ED);
            float rsA = rsqrtf(s2a * (1.0f / ED) - muA * muA + 1e-5f);
            float muB = s1b * (1.0f / ED);
            float rsB = rsqrtf(s2b * (1.0f / ED) - muB * muB + 1e-5f);

            #pragma unroll
            for (int nt = 0; nt < 8; ++nt) {
                int c = nt * 8 + qc;
                float2 gv = *(const float2*)&sLN_i[64 + c];
                float2 bv = *(const float2*)&sLN_i[128 + c];
                float r0 = fmaf((D[nt][0] - muA) * rsA, gv.x, bv.x);
                float r1 = fmaf((D[nt][1] - muA) * rsA, gv.y, bv.y);
                *(float2*)&Fsw[qr * 68 + c] = make_float2(r0, r1);
            }
            __syncwarp();
            if ((lane >> 3) == mt * 2) {
                #pragma unroll
                for (int q = 0; q < 32; ++q)
                    bb[q] = add2(bb[q], *(ull*)&Fsw[(lane & 7) * 68 + 2 * q]);
            }
            __syncwarp();
            #pragma unroll
            for (int nt = 0; nt < 8; ++nt) {
                int c = nt * 8 + qc;
                float2 gv = *(const float2*)&sLN_i[64 + c];
                float2 bv = *(const float2*)&sLN_i[128 + c];
                float r2 = fmaf((D[nt][2] - muB) * rsB, gv.x, bv.x);
                float r3 = fmaf((D[nt][3] - muB) * rsB, gv.y, bv.y);
                *(float2*)&Fsw[qr * 68 + c] = make_float2(r2, r3);
            }
            __syncwarp();
            if ((lane >> 3) == mt * 2 + 1) {
                #pragma unroll
                for (int q = 0; q < 32; ++q)
                    bb[q] = add2(bb[q], *(ull*)&Fsw[(lane & 7) * 68 + 2 * q]);
            }
            __syncwarp();
        }
    }

    // ===== epilogue: z-mean over 8-lane groups =====
    {
        int cell = p >> 3;
        int iy = cell & 127;
        int ix = cell >> 7;
        int cidx = iy * XD + ix;
        bool writer = (lane & 7) == 0;
        #pragma unroll
        for (int q = 0; q < 32; ++q) {
            float a, b; unpk(bb[q], a, b);
            #pragma unroll
            for (int o = 1; o < 8; o <<= 1) {
                a += __shfl_xor_sync(0xffffffffu, a, o);
                b += __shfl_xor_sync(0xffffffffu, b, o);
            }
            if (writer) {
                out[(2 * q)     * (XD * YD) + cidx] = a * 0.125f;
                out[(2 * q + 1) * (XD * YD) + cidx] = b * 0.125f;
            }
        }
    }
}

// ---------------------------------------------------------------------------
extern "C" void kernel_launch(void* const* d_in, const int* in_sizes, int n_in,
                              void* d_out, int out_size) {
    const float* Tv     = (const float*)d_in[0];
    const float* intr   = (const float*)d_in[1];
    const float* img    = (const float*)d_in[2];
    const float* bev_in = (const float*)d_in[3];
    const float* W_off  = (const float*)d_in[4];
    const float* b_off  = (const float*)d_in[5];
    const float* s_off  = (const float*)d_in[6];
    const float* W_w    = (const float*)d_in[7];
    const float* b_w    = (const float*)d_in[8];
    const float* W_l    = (const float*)d_in[9];
    const float* b_l    = (const float*)d_in[10];
    const float* ln_g   = (const float*)d_in[11];
    const float* ln_b   = (const float*)d_in[12];
    float* out = (float*)d_out;

    cudaFuncSetAttribute(bev_kernel, cudaFuncAttributeMaxDynamicSharedMemorySize, SM_TOTAL);

    transpose_img_kernel<<<HW / 32, 256>>>(img);
    bev_kernel<<<NPTS / 256, 256, SM_TOTAL>>>(Tv, intr, bev_in,
                                              W_off, b_off, s_off, W_w, b_w,
                                              W_l, b_l, ln_g, ln_b, out);
}

// round 15
// speedup vs baseline: 1.0599x; 1.0399x over previous
#include <cuda_runtime.h>
#include <cuda_fp16.h>
#include <cstdint>

#define XD 128
#define YD 128
#define ZD 8
#define ED 64
#define NITER 3
#define FHD 96
#define FWD 320
#define NPTS (XD*YD*ZD)
#define HW (FHD*FWD)

typedef unsigned long long ull;

__device__ __half g_imgTh[HW * ED];   // (H,W,C) fp16 image, 3.9 MB

__device__ __forceinline__ ull pk2(float x, float y) {
    ull r; asm("mov.b64 %0,{%1,%2};" : "=l"(r) : "f"(x), "f"(y)); return r;
}
__device__ __forceinline__ ull splat(float x) { return pk2(x, x); }
__device__ __forceinline__ void unpk(ull v, float& x, float& y) {
    asm("mov.b64 {%0,%1},%2;" : "=f"(x), "=f"(y) : "l"(v));
}
__device__ __forceinline__ ull fma2(ull a, ull b, ull c) {
    ull d; asm("fma.rn.f32x2 %0,%1,%2,%3;" : "=l"(d) : "l"(a), "l"(b), "l"(c)); return d;
}
__device__ __forceinline__ ull add2(ull a, ull b) {
    ull d; asm("add.rn.f32x2 %0,%1,%2;" : "=l"(d) : "l"(a), "l"(b)); return d;
}
__device__ __forceinline__ uint32_t smem_u32(const void* p) {
    uint32_t a; asm("{ .reg .u64 t; cvta.to.shared.u64 t, %1; cvt.u32.u64 %0, t; }" : "=r"(a) : "l"(p));
    return a;
}

#define SWZ(off) ((off) ^ (((off) >> 3) & 0x70))

__device__ __forceinline__ void ldsm_x4(uint32_t& r0, uint32_t& r1, uint32_t& r2, uint32_t& r3,
                                        uint32_t addr) {
    asm volatile("ldmatrix.sync.aligned.m8n8.x4.shared.b16 {%0,%1,%2,%3}, [%4];"
                 : "=r"(r0), "=r"(r1), "=r"(r2), "=r"(r3) : "r"(addr));
}
__device__ __forceinline__ void ldsm_x4t(uint32_t& r0, uint32_t& r1, uint32_t& r2, uint32_t& r3,
                                         uint32_t addr) {
    asm volatile("ldmatrix.sync.aligned.m8n8.x4.trans.shared.b16 {%0,%1,%2,%3}, [%4];"
                 : "=r"(r0), "=r"(r1), "=r"(r2), "=r"(r3) : "r"(addr));
}
__device__ __forceinline__ void mma16816(float& d0, float& d1, float& d2, float& d3,
                                         uint32_t a0, uint32_t a1, uint32_t a2, uint32_t a3,
                                         uint32_t b0, uint32_t b1) {
    asm volatile("mma.sync.aligned.m16n8k16.row.col.f32.f16.f16.f32 "
                 "{%0,%1,%2,%3}, {%4,%5,%6,%7}, {%8,%9}, {%0,%1,%2,%3};"
                 : "+f"(d0), "+f"(d1), "+f"(d2), "+f"(d3)
                 : "r"(a0), "r"(a1), "r"(a2), "r"(a3), "r"(b0), "r"(b1));
}

// smem byte layout (86272 B -> 2 CTAs/SM, ~56KB left for L1D)
#define SM_AS    0        // 8 x 4096: gather table, then Ah|Al half-tiles
#define SM_WBH   32768    // 3 x 8192 fp16 Bh tiles (rows e, SW128)
#define SM_WD    57344    // 3 x 768 floats packed dot weights
#define SM_LN    66560    // 3 x 192 floats: b_l | ln_g | ln_b
#define SM_FS    68864    // 8 warps x 544 floats transpose buffer [8][68]
#define SM_TOTAL 86272

// ---------------------------------------------------------------------------
__global__ __launch_bounds__(256) void transpose_img_kernel(const float* __restrict__ img) {
    __shared__ float tile[32][65];
    const int r0 = blockIdx.x * 32;
    const int t  = threadIdx.x;
    const int tx = t & 31, ty = t >> 5;
    #pragma unroll
    for (int k = 0; k < 8; ++k) {
        int c = k * 8 + ty;
        tile[tx][c] = img[c * HW + r0 + tx];
    }
    __syncthreads();
    #pragma unroll
    for (int k = 0; k < 8; ++k) {
        int row = k * 4 + (t >> 6);
        int c   = t & 63;
        g_imgTh[(r0 + row) * ED + c] = __float2half(tile[row][c]);
    }
}

// ---------------------------------------------------------------------------
__global__ __launch_bounds__(256, 2) void bev_kernel(
    const float* __restrict__ Tv,     const float* __restrict__ intr,
    const float* __restrict__ bev_in,
    const float* __restrict__ W_off,  const float* __restrict__ b_off,
    const float* __restrict__ s_off,  const float* __restrict__ W_w,
    const float* __restrict__ b_w,
    const float* __restrict__ W_l,    const float* __restrict__ b_l,
    const float* __restrict__ ln_g,   const float* __restrict__ ln_b,
    float* __restrict__ out)
{
    extern __shared__ char smem[];
    const uint32_t smb = smem_u32(smem);
    float* sWd = (float*)(smem + SM_WD);
    float* sLN = (float*)(smem + SM_LN);
    const int t    = threadIdx.x;
    const int warp = t >> 5;
    const int lane = t & 31;
    char* tw   = smem + SM_AS + warp * 4096;            // table / Ah|Al half-tiles
    float* Fsw = (float*)(smem + SM_FS) + warp * 544;   // [8][68]
    const uint32_t asw = smb + SM_AS + warp * 4096;

    const int p = blockIdx.x * 256 + t;

    // ---- stage W_l as fp16 Bh tiles (rows e, SW128) ----
    for (int idx = t; idx < NITER * 4096; idx += 256) {
        int i = idx >> 12;
        int r = idx & 4095;
        int e = r >> 6, c = r & 63;
        uint32_t off = SWZ((uint32_t)(e * 128 + c * 2));
        *(__half*)(smem + SM_WBH + i * 8192 + off) = __float2half(W_l[idx]);
    }
    // ---- stage packed dot weights ----
    #pragma unroll
    for (int u = 0; u < 9; ++u) {
        int idx = t + u * 256;
        int i = idx / 768;
        int r = idx - i * 768;
        int e = r / 12, j = r - e * 12;
        float v = 0.0f;
        if (j < 6)      v = W_off[i * 384 + e * 6 + j];
        else if (j < 9) v = W_w[i * 192 + e * 3 + (j - 6)];
        sWd[idx] = v;
    }
    // ---- stage LN params ----
    for (int idx = t; idx < NITER * 192; idx += 256) {
        int i = idx / 192;
        int r = idx - i * 192;
        int j = r >> 6, e = r & 63;
        float v = (j == 0) ? b_l[i * ED + e] : (j == 1) ? ln_g[i * ED + e] : ln_b[i * ED + e];
        sLN[idx] = v;
    }

    // ---- projected base coords ----
    float pxb, pyb;
    {
        int iz = p & 7;
        int ixy = p >> 3;
        int iy = ixy & 127;
        int ix = ixy >> 7;
        float gx = (float)ix * 0.8f;
        float gy = 51.2f - (float)iy * 0.8f;
        float gz = (float)iz * 0.5f - 2.5f;
        float q0 = Tv[0]*gx + Tv[1]*gy + Tv[2]*gz  + Tv[3];
        float q1 = Tv[4]*gx + Tv[5]*gy + Tv[6]*gz  + Tv[7];
        float q2 = Tv[8]*gx + Tv[9]*gy + Tv[10]*gz + Tv[11];
        float r0 = intr[0]*q0 + intr[1]*q1 + intr[2]*q2;
        float r1 = intr[3]*q0 + intr[4]*q1 + intr[5]*q2;
        float r2 = intr[6]*q0 + intr[7]*q1 + intr[8]*q2;
        float invz = 1.0f / r2;
        float cx = r0 * invz * (1.0f / 640.0f) - 1.0f;
        float cy = r1 * invz * (1.0f / 192.0f) - 1.0f;
        pxb = cx * 160.0f + 159.5f;
        pyb = cy * 48.0f  + 47.5f;
    }

    // ---- load B state into registers (smem transpose, 8-row groups) ----
    ull bb[32];
    const int pwarp0 = blockIdx.x * 256 + warp * 32;
    #pragma unroll
    for (int g = 0; g < 4; ++g) {
        #pragma unroll
        for (int q = 0; q < 8; ++q) {
            int pt = pwarp0 + g * 8 + q;
            ull v = *((const ull*)(bev_in + (size_t)pt * ED) + lane);
            *(ull*)&Fsw[q * 68 + 2 * lane] = v;
        }
        __syncwarp();
        if ((lane >> 3) == g) {
            #pragma unroll
            for (int q = 0; q < 32; ++q)
                bb[q] = *(ull*)&Fsw[(lane & 7) * 68 + 2 * q];
        }
        __syncwarp();
    }

    __syncthreads();   // weights staged

    for (int i = 0; i < NITER; ++i) {
        const float* sWd_i = sWd + i * 768;
        const float* sLN_i = sLN + i * 192;
        const uint32_t wbh_i = smb + SM_WBH + i * 8192;

        // ===== dots: 10 logits, broadcast weight rows =====
        float d[10];
        {
            ull acc[5] = {0, 0, 0, 0, 0};
            #pragma unroll
            for (int ep = 0; ep < 32; ++ep) {
                float be0, be1; unpk(bb[ep], be0, be1);
                ull bs0 = splat(be0), bs1 = splat(be1);
                const ulonglong2* w0 = (const ulonglong2*)&sWd_i[(2 * ep) * 12];
                const ulonglong2* w1 = (const ulonglong2*)&sWd_i[(2 * ep + 1) * 12];
                ulonglong2 wa = w0[0], wb = w0[1], wc = w0[2];
                acc[0] = fma2(bs0, wa.x, acc[0]); acc[1] = fma2(bs0, wa.y, acc[1]);
                acc[2] = fma2(bs0, wb.x, acc[2]); acc[3] = fma2(bs0, wb.y, acc[3]);
                acc[4] = fma2(bs0, wc.x, acc[4]);
                wa = w1[0]; wb = w1[1]; wc = w1[2];
                acc[0] = fma2(bs1, wa.x, acc[0]); acc[1] = fma2(bs1, wa.y, acc[1]);
                acc[2] = fma2(bs1, wb.x, acc[2]); acc[3] = fma2(bs1, wb.y, acc[3]);
                acc[4] = fma2(bs1, wc.x, acc[4]);
            }
            #pragma unroll
            for (int q = 0; q < 5; ++q) unpk(acc[q], d[2 * q], d[2 * q + 1]);
        }

        // ===== G1: offsets/softmax -> gather table (SWZ rows) =====
        {
            const float sc = __ldg(s_off + i);
            float off[6];
            #pragma unroll
            for (int j = 0; j < 6; ++j) off[j] = (d[j] + __ldg(b_off + i * 6 + j)) * sc;
            float l0 = d[6] + __ldg(b_w + i * 3 + 0);
            float l1 = d[7] + __ldg(b_w + i * 3 + 1);
            float l2 = d[8] + __ldg(b_w + i * 3 + 2);
            float mx = fmaxf(l0, fmaxf(l1, l2));
            float e0 = __expf(l0 - mx), e1 = __expf(l1 - mx), e2 = __expf(l2 - mx);
            float inv = 1.0f / (e0 + e1 + e2);
            float wk[3] = {e0 * inv, e1 * inv, e2 * inv};
            #pragma unroll
            for (int k = 0; k < 3; ++k) {
                float px = fmaf(off[2 * k],     160.0f, pxb);
                float py = fmaf(off[2 * k + 1],  48.0f, pyb);
                float fx = floorf(px), fy = floorf(py);
                int x0 = (int)fx, y0 = (int)fy;
                float wx1 = px - fx, wy1 = py - fy;
                float wx0 = 1.0f - wx1, wy0 = 1.0f - wy1;
                bool vx0 = (unsigned)x0 < (unsigned)FWD, vx1 = (unsigned)(x0 + 1) < (unsigned)FWD;
                bool vy0 = (unsigned)y0 < (unsigned)FHD, vy1 = (unsigned)(y0 + 1) < (unsigned)FHD;
                int xc0 = min(max(x0, 0), FWD - 1), xc1 = min(max(x0 + 1, 0), FWD - 1);
                int yc0 = min(max(y0, 0), FHD - 1), yc1 = min(max(y0 + 1, 0), FHD - 1);
                int rA = yc0 * FWD, rB = yc1 * FWD;
                float W = wk[k];
                float w00 = (vx0 && vy0) ? W * wx0 * wy0 : 0.0f;
                float w01 = (vx1 && vy0) ? W * wx1 * wy0 : 0.0f;
                float w10 = (vx0 && vy1) ? W * wx0 * wy1 : 0.0f;
                float w11 = (vx1 && vy1) ? W * wx1 * wy1 : 0.0f;
                *(float4*)(tw + SWZ((uint32_t)(lane * 128 + k * 32))) = make_float4(
                    __int_as_float((rA + xc0) << 6), __int_as_float((rA + xc1) << 6),
                    __int_as_float((rB + xc0) << 6), __int_as_float((rB + xc1) << 6));
                *(float4*)(tw + SWZ((uint32_t)(lane * 128 + k * 32 + 16))) =
                    make_float4(w00, w01, w10, w11);
            }
        }
        __syncwarp();

        // ===== G2: half-warp-per-point gather (fp16 image), split chains =====
        {
            const int half16 = lane >> 4;
            const int li     = lane & 15;
            #pragma unroll 1
            for (int g = 0; g < 4; ++g) {
                #pragma unroll 2
                for (int qq = 0; qq < 4; ++qq) {
                    const int pt = g * 8 + qq * 2 + half16;
                    float4 A0  = *(const float4*)(tw + SWZ((uint32_t)(pt * 128 + 0)));
                    float4 W0  = *(const float4*)(tw + SWZ((uint32_t)(pt * 128 + 16)));
                    float4 A1  = *(const float4*)(tw + SWZ((uint32_t)(pt * 128 + 32)));
                    float4 W1  = *(const float4*)(tw + SWZ((uint32_t)(pt * 128 + 48)));
                    float4 A2  = *(const float4*)(tw + SWZ((uint32_t)(pt * 128 + 64)));
                    float4 W2  = *(const float4*)(tw + SWZ((uint32_t)(pt * 128 + 80)));
                    ull accA0 = 0, accA1 = 0, accB0 = 0, accB1 = 0;
                    #pragma unroll
                    for (int k = 0; k < 3; ++k) {
                        float4 A  = (k == 0) ? A0 : (k == 1) ? A1 : A2;
                        float4 Wt = (k == 0) ? W0 : (k == 1) ? W1 : W2;
                        #pragma unroll
                        for (int c = 0; c < 4; ++c) {
                            int   base = __float_as_int(c == 0 ? A.x : c == 1 ? A.y : c == 2 ? A.z : A.w);
                            float wgt  =                (c == 0 ? Wt.x : c == 1 ? Wt.y : c == 2 ? Wt.z : Wt.w);
                            uint2 raw = *(const uint2*)(g_imgTh + base + 4 * li);
                            float2 v0 = __half22float2(*(__half2*)&raw.x);
                            float2 v1 = __half22float2(*(__half2*)&raw.y);
                            ull ws = splat(wgt);
                            if (k == 1) {
                                accB0 = fma2(ws, pk2(v0.x, v0.y), accB0);
                                accB1 = fma2(ws, pk2(v1.x, v1.y), accB1);
                            } else {
                                accA0 = fma2(ws, pk2(v0.x, v0.y), accA0);
                                accA1 = fma2(ws, pk2(v1.x, v1.y), accA1);
                            }
                        }
                    }
                    ull acc0 = add2(accA0, accB0);
                    ull acc1 = add2(accA1, accB1);
                    float a0, a1, a2, a3;
                    unpk(acc0, a0, a1); unpk(acc1, a2, a3);
                    *(float4*)&Fsw[(qq * 2 + half16) * 68 + 4 * li] =
                        make_float4(a0, a1, a2, a3);
                }
                __syncwarp();
                if ((lane >> 3) == g) {
                    #pragma unroll
                    for (int q = 0; q < 32; ++q)
                        bb[q] = add2(bb[q], *(ull*)&Fsw[(lane & 7) * 68 + 2 * q]);
                }
                __syncwarp();
            }
        }

        // ===== matvec: 2-term split-precision mma.sync (AhBh + AlBh) =====
        const int qr = lane >> 2;
        const int qc = (lane & 3) * 2;
        #pragma unroll
        for (int mt = 0; mt < 2; ++mt) {
            if ((lane >> 4) == mt) {
                int row = lane & 15;
                #pragma unroll
                for (int cb = 0; cb < 8; ++cb) {
                    uint32_t hv[4], lv[4];
                    #pragma unroll
                    for (int j = 0; j < 4; ++j) {
                        float a, b; unpk(bb[4 * cb + j], a, b);
                        __half2 hh = __floats2half2_rn(a, b);
                        float2 bk = __half22float2(hh);
                        __half2 ll = __floats2half2_rn(a - bk.x, b - bk.y);
                        hv[j] = *(uint32_t*)&hh;
                        lv[j] = *(uint32_t*)&ll;
                    }
                    uint32_t off = SWZ((uint32_t)(row * 128 + cb * 16));
                    *(uint4*)(tw + off)        = make_uint4(hv[0], hv[1], hv[2], hv[3]);
                    *(uint4*)(tw + 2048 + off) = make_uint4(lv[0], lv[1], lv[2], lv[3]);
                }
            }
            __syncwarp();

            float D[8][4];
            #pragma unroll
            for (int nt = 0; nt < 8; ++nt) {
                float2 bv = *(const float2*)&sLN_i[nt * 8 + qc];
                D[nt][0] = bv.x; D[nt][1] = bv.y;
                D[nt][2] = bv.x; D[nt][3] = bv.y;
            }
            const uint32_t arow = (uint32_t)(lane & 15);
            const uint32_t koff8 = (uint32_t)(((lane >> 4) & 1) << 3);
            #pragma unroll
            for (int kt = 0; kt < 4; ++kt) {
                uint32_t ah0, ah1, ah2, ah3, al0, al1, al2, al3;
                uint32_t aoff = SWZ(arow * 128 + (kt * 16 + koff8) * 2);
                ldsm_x4(ah0, ah1, ah2, ah3, asw + aoff);
                ldsm_x4(al0, al1, al2, al3, asw + 2048 + aoff);
                const uint32_t brow = (uint32_t)(kt * 16 + (lane & 15));
                #pragma unroll
                for (int np = 0; np < 4; ++np) {
                    uint32_t boff = SWZ(brow * 128 + (np * 16 + koff8) * 2);
                    uint32_t bh0, bh1, bh2, bh3;
                    ldsm_x4t(bh0, bh1, bh2, bh3, wbh_i + boff);
                    mma16816(D[2*np][0],   D[2*np][1],   D[2*np][2],   D[2*np][3],
                             ah0, ah1, ah2, ah3, bh0, bh1);
                    mma16816(D[2*np+1][0], D[2*np+1][1], D[2*np+1][2], D[2*np+1][3],
                             ah0, ah1, ah2, ah3, bh2, bh3);
                    mma16816(D[2*np][0],   D[2*np][1],   D[2*np][2],   D[2*np][3],
                             al0, al1, al2, al3, bh0, bh1);
                    mma16816(D[2*np+1][0], D[2*np+1][1], D[2*np+1][2], D[2*np+1][3],
                             al0, al1, al2, al3, bh2, bh3);
                }
            }
            float s1a = 0.f, s2a = 0.f, s1b = 0.f, s2b = 0.f;
            #pragma unroll
            for (int nt = 0; nt < 8; ++nt) {
                s1a += D[nt][0] + D[nt][1];
                s2a = fmaf(D[nt][0], D[nt][0], s2a); s2a = fmaf(D[nt][1], D[nt][1], s2a);
                s1b += D[nt][2] + D[nt][3];
                s2b = fmaf(D[nt][2], D[nt][2], s2b); s2b = fmaf(D[nt][3], D[nt][3], s2b);
            }
            #pragma unroll
            for (int o = 1; o < 4; o <<= 1) {
                s1a += __shfl_xor_sync(0xffffffffu, s1a, o);
                s2a += __shfl_xor_sync(0xffffffffu, s2a, o);
                s1b += __shfl_xor_sync(0xffffffffu, s1b, o);
                s2b += __shfl_xor_sync(0xffffffffu, s2b, o);
            }
            float muA = s1a * (1.0f / ED);
            float rsA = rsqrtf(s2a * (1.0f / ED) - muA * muA + 1e-5f);
            float muB = s1b * (1.0f / ED);
            float rsB = rsqrtf(s2b * (1.0f / ED) - muB * muB + 1e-5f);

            #pragma unroll
            for (int nt = 0; nt < 8; ++nt) {
                int c = nt * 8 + qc;
                float2 gv = *(const float2*)&sLN_i[64 + c];
                float2 bv = *(const float2*)&sLN_i[128 + c];
                float r0 = fmaf((D[nt][0] - muA) * rsA, gv.x, bv.x);
                float r1 = fmaf((D[nt][1] - muA) * rsA, gv.y, bv.y);
                *(float2*)&Fsw[qr * 68 + c] = make_float2(r0, r1);
            }
            __syncwarp();
            if ((lane >> 3) == mt * 2) {
                #pragma unroll
                for (int q = 0; q < 32; ++q)
                    bb[q] = add2(bb[q], *(ull*)&Fsw[(lane & 7) * 68 + 2 * q]);
            }
            __syncwarp();
            #pragma unroll
            for (int nt = 0; nt < 8; ++nt) {
                int c = nt * 8 + qc;
                float2 gv = *(const float2*)&sLN_i[64 + c];
                float2 bv = *(const float2*)&sLN_i[128 + c];
                float r2 = fmaf((D[nt][2] - muB) * rsB, gv.x, bv.x);
                float r3 = fmaf((D[nt][3] - muB) * rsB, gv.y, bv.y);
                *(float2*)&Fsw[qr * 68 + c] = make_float2(r2, r3);
            }
            __syncwarp();
            if ((lane >> 3) == mt * 2 + 1) {
                #pragma unroll
                for (int q = 0; q < 32; ++q)
                    bb[q] = add2(bb[q], *(ull*)&Fsw[(lane & 7) * 68 + 2 * q]);
            }
            __syncwarp();
        }
    }

    // ===== epilogue: z-mean over 8-lane groups =====
    {
        int cell = p >> 3;
        int iy = cell & 127;
        int ix = cell >> 7;
        int cidx = iy * XD + ix;
        bool writer = (lane & 7) == 0;
        #pragma unroll
        for (int q = 0; q < 32; ++q) {
            float a, b; unpk(bb[q], a, b);
            #pragma unroll
            for (int o = 1; o < 8; o <<= 1) {
                a += __shfl_xor_sync(0xffffffffu, a, o);
                b += __shfl_xor_sync(0xffffffffu, b, o);
            }
            if (writer) {
                out[(2 * q)     * (XD * YD) + cidx] = a * 0.125f;
                out[(2 * q + 1) * (XD * YD) + cidx] = b * 0.125f;
            }
        }
    }
}

// ---------------------------------------------------------------------------
extern "C" void kernel_launch(void* const* d_in, const int* in_sizes, int n_in,
                              void* d_out, int out_size) {
    const float* Tv     = (const float*)d_in[0];
    const float* intr   = (const float*)d_in[1];
    const float* img    = (const float*)d_in[2];
    const float* bev_in = (const float*)d_in[3];
    const float* W_off  = (const float*)d_in[4];
    const float* b_off  = (const float*)d_in[5];
    const float* s_off  = (const float*)d_in[6];
    const float* W_w    = (const float*)d_in[7];
    const float* b_w    = (const float*)d_in[8];
    const float* W_l    = (const float*)d_in[9];
    const float* b_l    = (const float*)d_in[10];
    const float* ln_g   = (const float*)d_in[11];
    const float* ln_b   = (const float*)d_in[12];
    float* out = (float*)d_out;

    cudaFuncSetAttribute(bev_kernel, cudaFuncAttributeMaxDynamicSharedMemorySize, SM_TOTAL);

    transpose_img_kernel<<<HW / 32, 256>>>(img);
    bev_kernel<<<NPTS / 256, 256, SM_TOTAL>>>(Tv, intr, bev_in,
                                              W_off, b_off, s_off, W_w, b_w,
                                              W_l, b_l, ln_g, ln_b, out);
}

// round 17
// speedup vs baseline: 1.1261x; 1.0625x over previous
#include <cuda_runtime.h>
#include <cuda_fp16.h>
#include <cstdint>

#define XD 128
#define YD 128
#define ZD 8
#define ED 64
#define NITER 3
#define FHD 96
#define FWD 320
#define NPTS (XD*YD*ZD)
#define HW (FHD*FWD)

typedef unsigned long long ull;

__device__ __half g_imgTh[HW * ED];   // (H,W,C) fp16 image, 3.9 MB

__device__ __forceinline__ ull pk2(float x, float y) {
    ull r; asm("mov.b64 %0,{%1,%2};" : "=l"(r) : "f"(x), "f"(y)); return r;
}
__device__ __forceinline__ ull splat(float x) { return pk2(x, x); }
__device__ __forceinline__ void unpk(ull v, float& x, float& y) {
    asm("mov.b64 {%0,%1},%2;" : "=f"(x), "=f"(y) : "l"(v));
}
__device__ __forceinline__ ull fma2(ull a, ull b, ull c) {
    ull d; asm("fma.rn.f32x2 %0,%1,%2,%3;" : "=l"(d) : "l"(a), "l"(b), "l"(c)); return d;
}
__device__ __forceinline__ ull add2(ull a, ull b) {
    ull d; asm("add.rn.f32x2 %0,%1,%2;" : "=l"(d) : "l"(a), "l"(b)); return d;
}
__device__ __forceinline__ uint32_t smem_u32(const void* p) {
    uint32_t a; asm("{ .reg .u64 t; cvta.to.shared.u64 t, %1; cvt.u32.u64 %0, t; }" : "=r"(a) : "l"(p));
    return a;
}

#define SWZ(off) ((off) ^ (((off) >> 3) & 0x70))

__device__ __forceinline__ void ldsm_x4(uint32_t& r0, uint32_t& r1, uint32_t& r2, uint32_t& r3,
                                        uint32_t addr) {
    asm volatile("ldmatrix.sync.aligned.m8n8.x4.shared.b16 {%0,%1,%2,%3}, [%4];"
                 : "=r"(r0), "=r"(r1), "=r"(r2), "=r"(r3) : "r"(addr));
}
__device__ __forceinline__ void ldsm_x4t(uint32_t& r0, uint32_t& r1, uint32_t& r2, uint32_t& r3,
                                         uint32_t addr) {
    asm volatile("ldmatrix.sync.aligned.m8n8.x4.trans.shared.b16 {%0,%1,%2,%3}, [%4];"
                 : "=r"(r0), "=r"(r1), "=r"(r2), "=r"(r3) : "r"(addr));
}
__device__ __forceinline__ void mma16816(float& d0, float& d1, float& d2, float& d3,
                                         uint32_t a0, uint32_t a1, uint32_t a2, uint32_t a3,
                                         uint32_t b0, uint32_t b1) {
    asm volatile("mma.sync.aligned.m16n8k16.row.col.f32.f16.f16.f32 "
                 "{%0,%1,%2,%3}, {%4,%5,%6,%7}, {%8,%9}, {%0,%1,%2,%3};"
                 : "+f"(d0), "+f"(d1), "+f"(d2), "+f"(d3)
                 : "r"(a0), "r"(a1), "r"(a2), "r"(a3), "r"(b0), "r"(b1));
}

// smem byte layout (103680 B -> 2 CTAs/SM)
#define SM_AS    0        // 8 x 4096: gather table, then Ah|Al half-tiles
#define SM_WBH   32768    // 3 x 8192 fp16 Bh tiles (rows e, SW128)
#define SM_WD    57344    // 3 x 768 floats packed dot weights
#define SM_LN    66560    // 3 x 192 floats: b_l | ln_g | ln_b
#define SM_FS    68864    // 8 warps x 1088 floats transpose buffer [16][68]
#define SM_TOTAL 103680

// ---------------------------------------------------------------------------
__global__ __launch_bounds__(256) void transpose_img_kernel(const float* __restrict__ img) {
    __shared__ float tile[32][65];
    const int r0 = blockIdx.x * 32;
    const int t  = threadIdx.x;
    const int tx = t & 31, ty = t >> 5;
    #pragma unroll
    for (int k = 0; k < 8; ++k) {
        int c = k * 8 + ty;
        tile[tx][c] = img[c * HW + r0 + tx];
    }
    __syncthreads();
    #pragma unroll
    for (int k = 0; k < 8; ++k) {
        int row = k * 4 + (t >> 6);
        int c   = t & 63;
        g_imgTh[(r0 + row) * ED + c] = __float2half(tile[row][c]);
    }
}

// ---------------------------------------------------------------------------
__global__ __launch_bounds__(256, 2) void bev_kernel(
    const float* __restrict__ Tv,     const float* __restrict__ intr,
    const float* __restrict__ bev_in,
    const float* __restrict__ W_off,  const float* __restrict__ b_off,
    const float* __restrict__ s_off,  const float* __restrict__ W_w,
    const float* __restrict__ b_w,
    const float* __restrict__ W_l,    const float* __restrict__ b_l,
    const float* __restrict__ ln_g,   const float* __restrict__ ln_b,
    float* __restrict__ out)
{
    extern __shared__ char smem[];
    const uint32_t smb = smem_u32(smem);
    float* sWd = (float*)(smem + SM_WD);
    float* sLN = (float*)(smem + SM_LN);
    const int t    = threadIdx.x;
    const int warp = t >> 5;
    const int lane = t & 31;
    char* tw   = smem + SM_AS + warp * 4096;             // table / Ah|Al half-tiles
    float* Fsw = (float*)(smem + SM_FS) + warp * 1088;   // [16][68]
    const uint32_t asw = smb + SM_AS + warp * 4096;

    const int p = blockIdx.x * 256 + t;

    // ---- stage W_l as fp16 Bh tiles (rows e, SW128) ----
    for (int idx = t; idx < NITER * 4096; idx += 256) {
        int i = idx >> 12;
        int r = idx & 4095;
        int e = r >> 6, c = r & 63;
        uint32_t off = SWZ((uint32_t)(e * 128 + c * 2));
        *(__half*)(smem + SM_WBH + i * 8192 + off) = __float2half(W_l[idx]);
    }
    // ---- stage packed dot weights ----
    #pragma unroll
    for (int u = 0; u < 9; ++u) {
        int idx = t + u * 256;
        int i = idx / 768;
        int r = idx - i * 768;
        int e = r / 12, j = r - e * 12;
        float v = 0.0f;
        if (j < 6)      v = W_off[i * 384 + e * 6 + j];
        else if (j < 9) v = W_w[i * 192 + e * 3 + (j - 6)];
        sWd[idx] = v;
    }
    // ---- stage LN params ----
    for (int idx = t; idx < NITER * 192; idx += 256) {
        int i = idx / 192;
        int r = idx - i * 192;
        int j = r >> 6, e = r & 63;
        float v = (j == 0) ? b_l[i * ED + e] : (j == 1) ? ln_g[i * ED + e] : ln_b[i * ED + e];
        sLN[idx] = v;
    }

    // ---- projected base coords ----
    float pxb, pyb;
    {
        int iz = p & 7;
        int ixy = p >> 3;
        int iy = ixy & 127;
        int ix = ixy >> 7;
        float gx = (float)ix * 0.8f;
        float gy = 51.2f - (float)iy * 0.8f;
        float gz = (float)iz * 0.5f - 2.5f;
        float q0 = Tv[0]*gx + Tv[1]*gy + Tv[2]*gz  + Tv[3];
        float q1 = Tv[4]*gx + Tv[5]*gy + Tv[6]*gz  + Tv[7];
        float q2 = Tv[8]*gx + Tv[9]*gy + Tv[10]*gz + Tv[11];
        float r0 = intr[0]*q0 + intr[1]*q1 + intr[2]*q2;
        float r1 = intr[3]*q0 + intr[4]*q1 + intr[5]*q2;
        float r2 = intr[6]*q0 + intr[7]*q1 + intr[8]*q2;
        float invz = 1.0f / r2;
        float cx = r0 * invz * (1.0f / 640.0f) - 1.0f;
        float cy = r1 * invz * (1.0f / 192.0f) - 1.0f;
        pxb = cx * 160.0f + 159.5f;
        pyb = cy * 48.0f  + 47.5f;
    }

    // ---- load B state into registers (smem transpose, 16-row groups) ----
    ull bb[32];
    const int pwarp0 = blockIdx.x * 256 + warp * 32;
    #pragma unroll
    for (int g = 0; g < 2; ++g) {
        #pragma unroll
        for (int q = 0; q < 16; ++q) {
            int pt = pwarp0 + g * 16 + q;
            ull v = *((const ull*)(bev_in + (size_t)pt * ED) + lane);
            *(ull*)&Fsw[q * 68 + 2 * lane] = v;
        }
        __syncwarp();
        if ((lane >> 4) == g) {
            #pragma unroll
            for (int q = 0; q < 32; ++q)
                bb[q] = *(ull*)&Fsw[(lane & 15) * 68 + 2 * q];
        }
        __syncwarp();
    }

    __syncthreads();   // weights staged

    for (int i = 0; i < NITER; ++i) {
        const float* sWd_i = sWd + i * 768;
        const float* sLN_i = sLN + i * 192;
        const uint32_t wbh_i = smb + SM_WBH + i * 8192;

        // ===== dots: 10 logits, broadcast weight rows =====
        float d[10];
        {
            ull acc[5] = {0, 0, 0, 0, 0};
            #pragma unroll
            for (int ep = 0; ep < 32; ++ep) {
                float be0, be1; unpk(bb[ep], be0, be1);
                ull bs0 = splat(be0), bs1 = splat(be1);
                const ulonglong2* w0 = (const ulonglong2*)&sWd_i[(2 * ep) * 12];
                const ulonglong2* w1 = (const ulonglong2*)&sWd_i[(2 * ep + 1) * 12];
                ulonglong2 wa = w0[0], wb = w0[1], wc = w0[2];
                acc[0] = fma2(bs0, wa.x, acc[0]); acc[1] = fma2(bs0, wa.y, acc[1]);
                acc[2] = fma2(bs0, wb.x, acc[2]); acc[3] = fma2(bs0, wb.y, acc[3]);
                acc[4] = fma2(bs0, wc.x, acc[4]);
                wa = w1[0]; wb = w1[1]; wc = w1[2];
                acc[0] = fma2(bs1, wa.x, acc[0]); acc[1] = fma2(bs1, wa.y, acc[1]);
                acc[2] = fma2(bs1, wb.x, acc[2]); acc[3] = fma2(bs1, wb.y, acc[3]);
                acc[4] = fma2(bs1, wc.x, acc[4]);
            }
            #pragma unroll
            for (int q = 0; q < 5; ++q) unpk(acc[q], d[2 * q], d[2 * q + 1]);
        }

        // ===== G1: offsets/softmax -> gather table (SWZ rows) =====
        {
            const float sc = __ldg(s_off + i);
            float off[6];
            #pragma unroll
            for (int j = 0; j < 6; ++j) off[j] = (d[j] + __ldg(b_off + i * 6 + j)) * sc;
            float l0 = d[6] + __ldg(b_w + i * 3 + 0);
            float l1 = d[7] + __ldg(b_w + i * 3 + 1);
            float l2 = d[8] + __ldg(b_w + i * 3 + 2);
            float mx = fmaxf(l0, fmaxf(l1, l2));
            float e0 = __expf(l0 - mx), e1 = __expf(l1 - mx), e2 = __expf(l2 - mx);
            float inv = 1.0f / (e0 + e1 + e2);
            float wk[3] = {e0 * inv, e1 * inv, e2 * inv};
            #pragma unroll
            for (int k = 0; k < 3; ++k) {
                float px = fmaf(off[2 * k],     160.0f, pxb);
                float py = fmaf(off[2 * k + 1],  48.0f, pyb);
                float fx = floorf(px), fy = floorf(py);
                int x0 = (int)fx, y0 = (int)fy;
                float wx1 = px - fx, wy1 = py - fy;
                float wx0 = 1.0f - wx1, wy0 = 1.0f - wy1;
                bool vx0 = (unsigned)x0 < (unsigned)FWD, vx1 = (unsigned)(x0 + 1) < (unsigned)FWD;
                bool vy0 = (unsigned)y0 < (unsigned)FHD, vy1 = (unsigned)(y0 + 1) < (unsigned)FHD;
                int xc0 = min(max(x0, 0), FWD - 1), xc1 = min(max(x0 + 1, 0), FWD - 1);
                int yc0 = min(max(y0, 0), FHD - 1), yc1 = min(max(y0 + 1, 0), FHD - 1);
                int rA = yc0 * FWD, rB = yc1 * FWD;
                float W = wk[k];
                float w00 = (vx0 && vy0) ? W * wx0 * wy0 : 0.0f;
                float w01 = (vx1 && vy0) ? W * wx1 * wy0 : 0.0f;
                float w10 = (vx0 && vy1) ? W * wx0 * wy1 : 0.0f;
                float w11 = (vx1 && vy1) ? W * wx1 * wy1 : 0.0f;
                *(float4*)(tw + SWZ((uint32_t)(lane * 128 + k * 32))) = make_float4(
                    __int_as_float((rA + xc0) << 6), __int_as_float((rA + xc1) << 6),
                    __int_as_float((rB + xc0) << 6), __int_as_float((rB + xc1) << 6));
                *(float4*)(tw + SWZ((uint32_t)(lane * 128 + k * 32 + 16))) =
                    make_float4(w00, w01, w10, w11);
            }
        }
        __syncwarp();

        // ===== G2: half-warp-per-point gather, 16-point groups =====
        {
            const int half16 = lane >> 4;
            const int li     = lane & 15;
            #pragma unroll 1
            for (int g = 0; g < 2; ++g) {
                #pragma unroll 2
                for (int qq = 0; qq < 8; ++qq) {
                    const int pt = g * 16 + qq * 2 + half16;
                    float4 A0  = *(const float4*)(tw + SWZ((uint32_t)(pt * 128 + 0)));
                    float4 W0  = *(const float4*)(tw + SWZ((uint32_t)(pt * 128 + 16)));
                    float4 A1  = *(const float4*)(tw + SWZ((uint32_t)(pt * 128 + 32)));
                    float4 W1  = *(const float4*)(tw + SWZ((uint32_t)(pt * 128 + 48)));
                    float4 A2  = *(const float4*)(tw + SWZ((uint32_t)(pt * 128 + 64)));
                    float4 W2  = *(const float4*)(tw + SWZ((uint32_t)(pt * 128 + 80)));
                    ull accA0 = 0, accA1 = 0, accB0 = 0, accB1 = 0;
                    #pragma unroll
                    for (int k = 0; k < 3; ++k) {
                        float4 A  = (k == 0) ? A0 : (k == 1) ? A1 : A2;
                        float4 Wt = (k == 0) ? W0 : (k == 1) ? W1 : W2;
                        #pragma unroll
                        for (int c = 0; c < 4; ++c) {
                            int   base = __float_as_int(c == 0 ? A.x : c == 1 ? A.y : c == 2 ? A.z : A.w);
                            float wgt  =                (c == 0 ? Wt.x : c == 1 ? Wt.y : c == 2 ? Wt.z : Wt.w);
                            uint2 raw = *(const uint2*)(g_imgTh + base + 4 * li);
                            float2 v0 = __half22float2(*(__half2*)&raw.x);
                            float2 v1 = __half22float2(*(__half2*)&raw.y);
                            ull ws = splat(wgt);
                            if (k == 1) {
                                accB0 = fma2(ws, pk2(v0.x, v0.y), accB0);
                                accB1 = fma2(ws, pk2(v1.x, v1.y), accB1);
                            } else {
                                accA0 = fma2(ws, pk2(v0.x, v0.y), accA0);
                                accA1 = fma2(ws, pk2(v1.x, v1.y), accA1);
                            }
                        }
                    }
                    ull acc0 = add2(accA0, accB0);
                    ull acc1 = add2(accA1, accB1);
                    float a0, a1, a2, a3;
                    unpk(acc0, a0, a1); unpk(acc1, a2, a3);
                    *(float4*)&Fsw[(qq * 2 + half16) * 68 + 4 * li] =
                        make_float4(a0, a1, a2, a3);
                }
                __syncwarp();
                if ((lane >> 4) == g) {
                    #pragma unroll
                    for (int q = 0; q < 32; ++q)
                        bb[q] = add2(bb[q], *(ull*)&Fsw[(lane & 15) * 68 + 2 * q]);
                }
                __syncwarp();
            }
        }

        // ===== matvec: 2-term split-precision mma.sync (AhBh + AlBh) =====
        const int qr = lane >> 2;
        const int qc = (lane & 3) * 2;
        #pragma unroll
        for (int mt = 0; mt < 2; ++mt) {
            if ((lane >> 4) == mt) {
                int row = lane & 15;
                #pragma unroll
                for (int cb = 0; cb < 8; ++cb) {
                    uint32_t hv[4], lv[4];
                    #pragma unroll
                    for (int j = 0; j < 4; ++j) {
                        float a, b; unpk(bb[4 * cb + j], a, b);
                        __half2 hh = __floats2half2_rn(a, b);
                        float2 bk = __half22float2(hh);
                        __half2 ll = __floats2half2_rn(a - bk.x, b - bk.y);
                        hv[j] = *(uint32_t*)&hh;
                        lv[j] = *(uint32_t*)&ll;
                    }
                    uint32_t off = SWZ((uint32_t)(row * 128 + cb * 16));
                    *(uint4*)(tw + off)        = make_uint4(hv[0], hv[1], hv[2], hv[3]);
                    *(uint4*)(tw + 2048 + off) = make_uint4(lv[0], lv[1], lv[2], lv[3]);
                }
            }
            __syncwarp();

            float D[8][4];
            #pragma unroll
            for (int nt = 0; nt < 8; ++nt) {
                float2 bv = *(const float2*)&sLN_i[nt * 8 + qc];
                D[nt][0] = bv.x; D[nt][1] = bv.y;
                D[nt][2] = bv.x; D[nt][3] = bv.y;
            }
            const uint32_t arow = (uint32_t)(lane & 15);
            const uint32_t koff8 = (uint32_t)(((lane >> 4) & 1) << 3);
            #pragma unroll
            for (int kt = 0; kt < 4; ++kt) {
                uint32_t ah0, ah1, ah2, ah3, al0, al1, al2, al3;
                uint32_t aoff = SWZ(arow * 128 + (kt * 16 + koff8) * 2);
                ldsm_x4(ah0, ah1, ah2, ah3, asw + aoff);
                ldsm_x4(al0, al1, al2, al3, asw + 2048 + aoff);
                const uint32_t brow = (uint32_t)(kt * 16 + (lane & 15));
                #pragma unroll
                for (int np = 0; np < 4; ++np) {
                    uint32_t boff = SWZ(brow * 128 + (np * 16 + koff8) * 2);
                    uint32_t bh0, bh1, bh2, bh3;
                    ldsm_x4t(bh0, bh1, bh2, bh3, wbh_i + boff);
                    mma16816(D[2*np][0],   D[2*np][1],   D[2*np][2],   D[2*np][3],
                             ah0, ah1, ah2, ah3, bh0, bh1);
                    mma16816(D[2*np+1][0], D[2*np+1][1], D[2*np+1][2], D[2*np+1][3],
                             ah0, ah1, ah2, ah3, bh2, bh3);
                    mma16816(D[2*np][0],   D[2*np][1],   D[2*np][2],   D[2*np][3],
                             al0, al1, al2, al3, bh0, bh1);
                    mma16816(D[2*np+1][0], D[2*np+1][1], D[2*np+1][2], D[2*np+1][3],
                             al0, al1, al2, al3, bh2, bh3);
                }
            }
            float s1a = 0.f, s2a = 0.f, s1b = 0.f, s2b = 0.f;
            #pragma unroll
            for (int nt = 0; nt < 8; ++nt) {
                s1a += D[nt][0] + D[nt][1];
                s2a = fmaf(D[nt][0], D[nt][0], s2a); s2a = fmaf(D[nt][1], D[nt][1], s2a);
                s1b += D[nt][2] + D[nt][3];
                s2b = fmaf(D[nt][2], D[nt][2], s2b); s2b = fmaf(D[nt][3], D[nt][3], s2b);
            }
            #pragma unroll
            for (int o = 1; o < 4; o <<= 1) {
                s1a += __shfl_xor_sync(0xffffffffu, s1a, o);
                s2a += __shfl_xor_sync(0xffffffffu, s2a, o);
                s1b += __shfl_xor_sync(0xffffffffu, s1b, o);
                s2b += __shfl_xor_sync(0xffffffffu, s2b, o);
            }
            float muA = s1a * (1.0f / ED);
            float rsA = rsqrtf(s2a * (1.0f / ED) - muA * muA + 1e-5f);
            float muB = s1b * (1.0f / ED);
            float rsB = rsqrtf(s2b * (1.0f / ED) - muB * muB + 1e-5f);

            // write BOTH row-halves, then one fold
            #pragma unroll
            for (int nt = 0; nt < 8; ++nt) {
                int c = nt * 8 + qc;
                float2 gv = *(const float2*)&sLN_i[64 + c];
                float2 bv = *(const float2*)&sLN_i[128 + c];
                float r0 = fmaf((D[nt][0] - muA) * rsA, gv.x, bv.x);
                float r1 = fmaf((D[nt][1] - muA) * rsA, gv.y, bv.y);
                *(float2*)&Fsw[qr * 68 + c] = make_float2(r0, r1);
                float r2 = fmaf((D[nt][2] - muB) * rsB, gv.x, bv.x);
                float r3 = fmaf((D[nt][3] - muB) * rsB, gv.y, bv.y);
                *(float2*)&Fsw[(qr + 8) * 68 + c] = make_float2(r2, r3);
            }
            __syncwarp();
            if ((lane >> 4) == mt) {
                #pragma unroll
                for (int q = 0; q < 32; ++q)
                    bb[q] = add2(bb[q], *(ull*)&Fsw[(lane & 15) * 68 + 2 * q]);
            }
            __syncwarp();
        }
    }

    // ===== epilogue: z-mean over 8-lane groups =====
    {
        int cell = p >> 3;
        int iy = cell & 127;
        int ix = cell >> 7;
        int cidx = iy * XD + ix;
        bool writer = (lane & 7) == 0;
        #pragma unroll
        for (int q = 0; q < 32; ++q) {
            float a, b; unpk(bb[q], a, b);
            #pragma unroll
            for (int o = 1; o < 8; o <<= 1) {
                a += __shfl_xor_sync(0xffffffffu, a, o);
                b += __shfl_xor_sync(0xffffffffu, b, o);
            }
            if (writer) {
                out[(2 * q)     * (XD * YD) + cidx] = a * 0.125f;
                out[(2 * q + 1) * (XD * YD) + cidx] = b * 0.125f;
            }
        }
    }
}

// ---------------------------------------------------------------------------
extern "C" void kernel_launch(void* const* d_in, const int* in_sizes, int n_in,
                              void* d_out, int out_size) {
    const float* Tv     = (const float*)d_in[0];
    const float* intr   = (const float*)d_in[1];
    const float* img    = (const float*)d_in[2];
    const float* bev_in = (const float*)d_in[3];
    const float* W_off  = (const float*)d_in[4];
    const float* b_off  = (const float*)d_in[5];
    const float* s_off  = (const float*)d_in[6];
    const float* W_w    = (const float*)d_in[7];
    const float* b_w    = (const float*)d_in[8];
    const float* W_l    = (const float*)d_in[9];
    const float* b_l    = (const float*)d_in[10];
    const float* ln_g   = (const float*)d_in[11];
    const float* ln_b   = (const float*)d_in[12];
    float* out = (float*)d_out;

    cudaFuncSetAttribute(bev_kernel, cudaFuncAttributeMaxDynamicSharedMemorySize, SM_TOTAL);

    transpose_img_kernel<<<HW / 32, 256>>>(img);
    bev_kernel<<<NPTS / 256, 256, SM_TOTAL>>>(Tv, intr, bev_in,
                                              W_off, b_off, s_off, W_w, b_w,
                                              W_l, b_l, ln_g, ln_b, out);
}